// round 7
// baseline (speedup 1.0000x reference)
#include <cuda_runtime.h>
#include <cuda_bf16.h>
#include <math.h>
#include <stdint.h>

// Problem constants
constexpr int BB = 512;      // batch (M)
constexpr int EE = 512;      // embedding dim (K)
constexpr int CC = 100000;   // classes (N)
constexpr int NT = (CC + 127) / 128;   // 782 N-tiles

// ArcFace constants (margin = 0.5)
#define COS_M   0.8775825618903728f
#define SIN_M   0.479425538604203f
#define MM_C    0.23971276930210156f
#define THRESH  (-0.8775825618903728f)
#define S_SCALE 64.0f

// ---------------------------------------------------------------------------
// Static device scratch (allocations are forbidden)
// ---------------------------------------------------------------------------
__device__ float         g_inv_norm[CC];
__device__ float         g_row_loss[BB];
__device__ float         g_partial[(size_t)BB * NT];
__device__ __nv_bfloat16 g_kT_hi[(size_t)CC * EE];   // knormT [C][K] hi
__device__ __nv_bfloat16 g_kT_lo[(size_t)CC * EE];   // knormT [C][K] lo
__device__ __nv_bfloat16 g_emb_hi[(size_t)BB * EE];  // emb [B][K] hi
__device__ __nv_bfloat16 g_emb_lo[(size_t)BB * EE];  // emb [B][K] lo

// ---------------------------------------------------------------------------
// PTX helpers: baseline (non-'a') instructions only
// ---------------------------------------------------------------------------
__device__ __forceinline__ uint32_t smem_u32(const void* p) {
    uint32_t a;
    asm("{ .reg .u64 t; cvta.to.shared.u64 t, %1; cvt.u32.u64 %0, t; }"
        : "=r"(a) : "l"(p));
    return a;
}

__device__ __forceinline__ void ldsm_x4(uint32_t* r, uint32_t a) {
    asm volatile("ldmatrix.sync.aligned.m8n8.x4.shared.b16 {%0,%1,%2,%3}, [%4];"
        : "=r"(r[0]), "=r"(r[1]), "=r"(r[2]), "=r"(r[3]) : "r"(a));
}
__device__ __forceinline__ void mma_bf16(float* d, const uint32_t* a, const uint32_t* b) {
    asm volatile(
        "mma.sync.aligned.m16n8k16.row.col.f32.bf16.bf16.f32 "
        "{%0,%1,%2,%3}, {%4,%5,%6,%7}, {%8,%9}, {%0,%1,%2,%3};"
        : "+f"(d[0]), "+f"(d[1]), "+f"(d[2]), "+f"(d[3])
        : "r"(a[0]), "r"(a[1]), "r"(a[2]), "r"(a[3]), "r"(b[0]), "r"(b[1]));
}
__device__ __forceinline__ void cp16(uint32_t dst, const void* src, int sz) {
    asm volatile("cp.async.cg.shared.global [%0], [%1], 16, %2;"
        :: "r"(dst), "l"(src), "r"(sz) : "memory");
}
#define CP_COMMIT() asm volatile("cp.async.commit_group;" ::: "memory")
#define CP_WAIT0()  asm volatile("cp.async.wait_group 0;" ::: "memory")

// ---------------------------------------------------------------------------
// Kernel 1: per-class column inverse norms
// ---------------------------------------------------------------------------
__global__ void norm_kernel(const float* __restrict__ ker) {
    int c = blockIdx.x * blockDim.x + threadIdx.x;
    if (c >= CC) return;
    float s0 = 0.f, s1 = 0.f, s2 = 0.f, s3 = 0.f;
    #pragma unroll 4
    for (int e = 0; e < EE; e += 4) {
        float v0 = ker[(size_t)(e + 0) * CC + c];
        float v1 = ker[(size_t)(e + 1) * CC + c];
        float v2 = ker[(size_t)(e + 2) * CC + c];
        float v3 = ker[(size_t)(e + 3) * CC + c];
        s0 = fmaf(v0, v0, s0);
        s1 = fmaf(v1, v1, s1);
        s2 = fmaf(v2, v2, s2);
        s3 = fmaf(v3, v3, s3);
    }
    g_inv_norm[c] = 1.0f / (sqrtf((s0 + s1) + (s2 + s3)) + 1e-6f);
}

// ---------------------------------------------------------------------------
// Kernel 2: normalize + transpose ker -> knormT [C][K], bf16 hi/lo split
// ---------------------------------------------------------------------------
__global__ __launch_bounds__(256) void prep_ker_kernel(const float* __restrict__ ker) {
    __shared__ float t[32][33];
    const int c0 = blockIdx.x * 32;
    const int k0 = blockIdx.y * 32;
    const int tx = threadIdx.x;
    const int ty = threadIdx.y;

    const float inv = g_inv_norm[c0 + tx];
    #pragma unroll
    for (int i = 0; i < 4; i++) {
        int k = ty + i * 8;
        t[k][tx] = ker[(size_t)(k0 + k) * CC + (c0 + tx)] * inv;
    }
    __syncthreads();
    #pragma unroll
    for (int i = 0; i < 4; i++) {
        int c = ty + i * 8;
        float v = t[tx][c];
        __nv_bfloat16 h = __float2bfloat16(v);
        __nv_bfloat16 l = __float2bfloat16(v - __bfloat162float(h));
        size_t dst = (size_t)(c0 + c) * EE + (k0 + tx);
        g_kT_hi[dst] = h;
        g_kT_lo[dst] = l;
    }
}

// ---------------------------------------------------------------------------
// Kernel 3: split emb to bf16 hi/lo
// ---------------------------------------------------------------------------
__global__ void prep_emb_kernel(const float* __restrict__ emb) {
    int i = blockIdx.x * blockDim.x + threadIdx.x;
    if (i >= BB * EE) return;
    float v = emb[i];
    __nv_bfloat16 h = __float2bfloat16(v);
    g_emb_hi[i] = h;
    g_emb_lo[i] = __float2bfloat16(v - __bfloat162float(h));
}

// ---------------------------------------------------------------------------
// Kernel 4: mma.sync bf16 split-3 GEMM + fused arcface epilogue.
// 256 threads, 2 CTAs/SM (<=128 regs), warp grid 2x4, warp tile 64x32.
// Warp-skewed kk/np order breaks the post-barrier LDSM convoy so the SMEM
// crossbar and the tensor pipe run concurrently across warps.
// ---------------------------------------------------------------------------
constexpr int ROWB   = 80;                    // padded row bytes (conflict-free)
constexpr int MATB   = 128 * ROWB;            // 10240 B per matrix
constexpr int STAGEB = 4 * MATB;              // 40960 B per stage
constexpr int DYNB   = 2 * STAGEB;            // 81920 B dynamic smem

__global__ __launch_bounds__(256, 2) void gemm_mma_kernel(
    const int* __restrict__ label,
    float* __restrict__ out_logits, float* __restrict__ out_cos)
{
    extern __shared__ char dyn[];
    const int tid  = threadIdx.x;
    const int lane = tid & 31;
    const int wid  = tid >> 5;
    const int wm   = wid >> 2;     // 0..1
    const int wn   = wid & 3;      // 0..3
    const int r0 = blockIdx.x * 128;
    const int c0 = blockIdx.y * 128;
    const uint32_t sbase = smem_u32(dyn);

    // phase skews (per-warp constants; deterministic)
    const int kk_skew = wid & 1;
    const int np_skew = (wid >> 1) & 1;

    // ---- G->S load mapping: 64 threads per matrix, 8 cp.async each ----
    const int mat  = tid >> 6;       // 0:Ahi 1:Alo 2:Bhi 3:Blo
    const int t6   = tid & 63;
    const int ch   = t6 & 3;
    const int rrow = t6 >> 2;
    const __nv_bfloat16* gp;
    if      (mat == 0) gp = g_emb_hi + (size_t)(r0 + rrow) * EE;
    else if (mat == 1) gp = g_emb_lo + (size_t)(r0 + rrow) * EE;
    else if (mat == 2) gp = g_kT_hi + (size_t)(c0 + rrow) * EE;
    else               gp = g_kT_lo + (size_t)(c0 + rrow) * EE;
    const bool isB = (mat >= 2);

    float acc[4][4][4];
    #pragma unroll
    for (int mt = 0; mt < 4; mt++)
        #pragma unroll
        for (int nt = 0; nt < 4; nt++)
            #pragma unroll
            for (int v = 0; v < 4; v++) acc[mt][nt][v] = 0.f;

    auto load_stage = [&](int s, int kc) {
        uint32_t dst0 = sbase + s * STAGEB + mat * MATB + rrow * ROWB + ch * 16;
        const __nv_bfloat16* p = gp + kc * 32 + ch * 8;
        #pragma unroll
        for (int j = 0; j < 8; j++) {
            int sz = 16;
            if (isB && (c0 + rrow + j * 16) >= CC) sz = 0;
            cp16(dst0 + j * 16 * ROWB, p + (size_t)j * 16 * EE, sz);
        }
    };

    // Term-major issue (same-acc MMAs 8 apart) + warp-skewed kk/np phases.
    auto compute_stage = [&](int s) {
        const uint32_t st = sbase + s * STAGEB;
        #pragma unroll
        for (int kki = 0; kki < 2; kki++) {
            const int kk = kki ^ kk_skew;
            uint32_t ah[4][4], al[4][4];
            #pragma unroll
            for (int mt = 0; mt < 4; mt++) {
                uint32_t ad = st + (uint32_t)((wm * 64 + mt * 16 + (lane & 15)) * ROWB
                                              + (lane >> 4) * 16 + kk * 32);
                ldsm_x4(ah[mt], ad);
                ldsm_x4(al[mt], ad + MATB);
            }
            #pragma unroll
            for (int npi = 0; npi < 2; npi++) {
                const int np = npi ^ np_skew;
                uint32_t bh[4], bl[4];
                uint32_t bd = st + 2 * MATB
                            + (uint32_t)((wn * 32 + (np * 2 + ((lane >> 4) & 1)) * 8
                                          + (lane & 7)) * ROWB
                                         + ((lane >> 3) & 1) * 16 + kk * 32);
                ldsm_x4(bh, bd);
                ldsm_x4(bl, bd + MATB);
                const int n0 = np * 2, n1 = np * 2 + 1;
                // term 1: hi*hi
                #pragma unroll
                for (int mt = 0; mt < 4; mt++) mma_bf16(acc[mt][n0], ah[mt], bh + 0);
                #pragma unroll
                for (int mt = 0; mt < 4; mt++) mma_bf16(acc[mt][n1], ah[mt], bh + 2);
                // term 2: hi*lo
                #pragma unroll
                for (int mt = 0; mt < 4; mt++) mma_bf16(acc[mt][n0], ah[mt], bl + 0);
                #pragma unroll
                for (int mt = 0; mt < 4; mt++) mma_bf16(acc[mt][n1], ah[mt], bl + 2);
                // term 3: lo*hi
                #pragma unroll
                for (int mt = 0; mt < 4; mt++) mma_bf16(acc[mt][n0], al[mt], bh + 0);
                #pragma unroll
                for (int mt = 0; mt < 4; mt++) mma_bf16(acc[mt][n1], al[mt], bh + 2);
            }
        }
    };

    // ---- pipeline: double-buffered over 16 K-chunks of 32 ----
    load_stage(0, 0);
    CP_COMMIT();
    CP_WAIT0();
    __syncthreads();
    for (int kc = 0; kc < 16; kc++) {
        if (kc < 15) { load_stage((kc + 1) & 1, kc + 1); CP_COMMIT(); }
        compute_stage(kc & 1);
        CP_WAIT0();
        __syncthreads();
    }

    // ---- epilogue: arcface + SCALAR stores + per-row partial sum-exp ----
    const int lq = lane >> 2;
    const int lc = 2 * (lane & 3);
    int lbs[4][2];
    #pragma unroll
    for (int mt = 0; mt < 4; mt++) {
        lbs[mt][0] = label[r0 + wm * 64 + mt * 16 + lq];
        lbs[mt][1] = label[r0 + wm * 64 + mt * 16 + lq + 8];
    }

    float rsum[4][2];
    #pragma unroll
    for (int mt = 0; mt < 4; mt++) { rsum[mt][0] = 0.f; rsum[mt][1] = 0.f; }

    const bool full_tile = (c0 + 128 <= CC);   // true for 781/782 strips

    #pragma unroll
    for (int mt = 0; mt < 4; mt++) {
        #pragma unroll
        for (int nt = 0; nt < 4; nt++) {
            #pragma unroll
            for (int v = 0; v < 4; v++) {
                const int h    = v >> 1;
                const int grow = r0 + wm * 64 + mt * 16 + lq + h * 8;
                const int col  = c0 + wn * 32 + nt * 8 + lc + (v & 1);
                if (full_tile || col < CC) {
                    float cs = acc[mt][nt][v];
                    cs = fminf(1.0f, fmaxf(-1.0f, cs));
                    float o = cs;
                    if (col == lbs[mt][h]) {
                        float sn = sqrtf(fmaxf(0.f, 1.0f - cs * cs));
                        float cm = fmaf(cs, COS_M, -sn * SIN_M);
                        o = (cs - THRESH <= 0.f) ? (cs - MM_C) : cm;
                    }
                    float lg = o * S_SCALE;
                    size_t ga = (size_t)grow * CC + col;
                    out_logits[ga] = lg;
                    out_cos[ga]    = cs;
                    rsum[mt][h] += __expf(lg - 64.0f);
                }
            }
        }
    }

    #pragma unroll
    for (int mt = 0; mt < 4; mt++)
        #pragma unroll
        for (int h = 0; h < 2; h++) {
            float s = rsum[mt][h];
            s += __shfl_xor_sync(0xffffffff, s, 1);
            s += __shfl_xor_sync(0xffffffff, s, 2);
            rsum[mt][h] = s;
        }

    float* srows = (float*)dyn;
    if ((lane & 3) == 0) {
        #pragma unroll
        for (int mt = 0; mt < 4; mt++)
            #pragma unroll
            for (int h = 0; h < 2; h++)
                srows[(wm * 64 + mt * 16 + lq + h * 8) * 4 + wn] = rsum[mt][h];
    }
    __syncthreads();
    if (tid < 128) {
        float s = srows[tid * 4 + 0] + srows[tid * 4 + 1]
                + srows[tid * 4 + 2] + srows[tid * 4 + 3];
        g_partial[(size_t)(r0 + tid) * NT + blockIdx.y] = s;
    }
}

// ---------------------------------------------------------------------------
// Kernel 5: per-row reduce of partial sum-exps -> row loss
// ---------------------------------------------------------------------------
__global__ void row_reduce_kernel(const float* __restrict__ out_logits,
                                  const int* __restrict__ label) {
    const int row = blockIdx.x;
    float s = 0.f;
    for (int i = threadIdx.x; i < NT; i += 256)
        s += g_partial[(size_t)row * NT + i];
    __shared__ float sm[256];
    sm[threadIdx.x] = s;
    __syncthreads();
    #pragma unroll
    for (int off = 128; off > 0; off >>= 1) {
        if (threadIdx.x < off) sm[threadIdx.x] += sm[threadIdx.x + off];
        __syncthreads();
    }
    if (threadIdx.x == 0) {
        float logZ = 64.0f + logf(sm[0]);
        g_row_loss[row] = logZ - out_logits[(size_t)row * CC + label[row]];
    }
}

// ---------------------------------------------------------------------------
// Kernel 6: mean over rows -> loss scalar
// ---------------------------------------------------------------------------
__global__ void final_loss_kernel(float* __restrict__ loss_out) {
    __shared__ float sm[BB];
    const int t = threadIdx.x;
    sm[t] = g_row_loss[t];
    __syncthreads();
    #pragma unroll
    for (int off = BB / 2; off > 0; off >>= 1) {
        if (t < off) sm[t] += sm[t + off];
        __syncthreads();
    }
    if (t == 0) loss_out[0] = sm[0] / (float)BB;
}

// ---------------------------------------------------------------------------
extern "C" void kernel_launch(void* const* d_in, const int* in_sizes, int n_in,
                              void* d_out, int out_size) {
    const float* emb   = (const float*)d_in[0];
    const float* ker   = (const float*)d_in[1];
    const int*   label = (const int*)d_in[2];

    float* o          = (float*)d_out;
    float* loss_ptr   = o;
    float* out_logits = o + 1;
    float* out_cos    = o + 1 + (size_t)BB * CC;

    cudaFuncSetAttribute(gemm_mma_kernel,
                         cudaFuncAttributeMaxDynamicSharedMemorySize, DYNB);

    norm_kernel<<<(CC + 255) / 256, 256>>>(ker);

    dim3 pg(CC / 32, EE / 32);
    prep_ker_kernel<<<pg, dim3(32, 8)>>>(ker);
    prep_emb_kernel<<<(BB * EE + 255) / 256, 256>>>(emb);

    dim3 grid(4, NT);   // x fastest: adjacent bids share the ker N-strip in L2
    gemm_mma_kernel<<<grid, 256, DYNB>>>(label, out_logits, out_cos);

    row_reduce_kernel<<<BB, 256>>>(out_logits, label);
    final_loss_kernel<<<1, BB>>>(loss_ptr);
}

// round 8
// speedup vs baseline: 2.1683x; 2.1683x over previous
#include <cuda_runtime.h>
#include <cuda_bf16.h>
#include <math.h>
#include <stdint.h>

// Problem constants
constexpr int BB = 512;      // batch (M)
constexpr int EE = 512;      // embedding dim (K)
constexpr int CC = 100000;   // classes (N)
constexpr int NT = (CC + 127) / 128;   // 782 N-tiles

// ArcFace constants (margin = 0.5)
#define COS_M   0.8775825618903728f
#define SIN_M   0.479425538604203f
#define MM_C    0.23971276930210156f
#define THRESH  (-0.8775825618903728f)
#define S_SCALE 64.0f

// ---------------------------------------------------------------------------
// Static device scratch (allocations are forbidden)
// ---------------------------------------------------------------------------
__device__ float         g_row_loss[BB];
__device__ float         g_partial[(size_t)BB * NT];
__device__ __nv_bfloat16 g_kT_hi[(size_t)CC * EE];   // knormT [C][K] hi
__device__ __nv_bfloat16 g_kT_lo[(size_t)CC * EE];   // knormT [C][K] lo
__device__ __nv_bfloat16 g_emb_hi[(size_t)BB * EE];  // emb [B][K] hi
__device__ __nv_bfloat16 g_emb_lo[(size_t)BB * EE];  // emb [B][K] lo

// ---------------------------------------------------------------------------
// PTX helpers: baseline (non-'a') instructions only
// ---------------------------------------------------------------------------
__device__ __forceinline__ uint32_t smem_u32(const void* p) {
    uint32_t a;
    asm("{ .reg .u64 t; cvta.to.shared.u64 t, %1; cvt.u32.u64 %0, t; }"
        : "=r"(a) : "l"(p));
    return a;
}

__device__ __forceinline__ void ldsm_x4(uint32_t* r, uint32_t a) {
    asm volatile("ldmatrix.sync.aligned.m8n8.x4.shared.b16 {%0,%1,%2,%3}, [%4];"
        : "=r"(r[0]), "=r"(r[1]), "=r"(r[2]), "=r"(r[3]) : "r"(a));
}
__device__ __forceinline__ void mma_bf16(float* d, const uint32_t* a, const uint32_t* b) {
    asm volatile(
        "mma.sync.aligned.m16n8k16.row.col.f32.bf16.bf16.f32 "
        "{%0,%1,%2,%3}, {%4,%5,%6,%7}, {%8,%9}, {%0,%1,%2,%3};"
        : "+f"(d[0]), "+f"(d[1]), "+f"(d[2]), "+f"(d[3])
        : "r"(a[0]), "r"(a[1]), "r"(a[2]), "r"(a[3]), "r"(b[0]), "r"(b[1]));
}
__device__ __forceinline__ void cp16(uint32_t dst, const void* src, int sz) {
    asm volatile("cp.async.cg.shared.global [%0], [%1], 16, %2;"
        :: "r"(dst), "l"(src), "r"(sz) : "memory");
}
#define CP_COMMIT() asm volatile("cp.async.commit_group;" ::: "memory")
#define CP_WAIT0()  asm volatile("cp.async.wait_group 0;" ::: "memory")

// ---------------------------------------------------------------------------
// Kernel 1 (fused): single pass over ker.
// Each CTA owns 32 classes: stage columns in SMEM, compute norms in-SMEM,
// write normalized transposed bf16 hi/lo. Reads ker once (was twice).
// ---------------------------------------------------------------------------
__global__ __launch_bounds__(256) void prep_ker_fused(const float* __restrict__ ker) {
    __shared__ float sm[32][513];    // [class][k], stride 513 -> conflict-free
    __shared__ float s_inv[32];

    const int tid  = threadIdx.x;
    const int lane = tid & 31;
    const int wid  = tid >> 5;
    const int c0   = blockIdx.x * 32;

    // Stage: coalesced read of ker[k][c0+lane], k strided by 8 warps
    #pragma unroll
    for (int i = 0; i < 64; i++) {
        int k = wid + i * 8;
        sm[lane][k] = ker[(size_t)k * CC + (c0 + lane)];
    }
    __syncthreads();

    // Norms: each warp reduces 4 columns (warp w -> cols w, w+8, w+16, w+24)
    #pragma unroll
    for (int i = 0; i < 4; i++) {
        int c = wid + i * 8;
        float s = 0.f;
        #pragma unroll
        for (int j = 0; j < 16; j++) {
            float v = sm[c][lane + j * 32];
            s = fmaf(v, v, s);
        }
        #pragma unroll
        for (int off = 16; off > 0; off >>= 1)
            s += __shfl_xor_sync(0xffffffff, s, off);
        if (lane == 0) s_inv[c] = 1.0f / (sqrtf(s) + 1e-6f);
    }
    __syncthreads();

    // Write transposed normalized hi/lo: warp w writes cols w, w+8, w+16, w+24
    #pragma unroll
    for (int i = 0; i < 4; i++) {
        int c = wid + i * 8;
        const float inv = s_inv[c];
        size_t base = (size_t)(c0 + c) * EE;
        #pragma unroll
        for (int j = 0; j < 16; j++) {
            int k = lane + j * 32;
            float v = sm[c][k] * inv;
            __nv_bfloat16 h = __float2bfloat16(v);
            g_kT_hi[base + k] = h;
            g_kT_lo[base + k] = __float2bfloat16(v - __bfloat162float(h));
        }
    }
}

// ---------------------------------------------------------------------------
// Kernel 2: split emb to bf16 hi/lo
// ---------------------------------------------------------------------------
__global__ void prep_emb_kernel(const float* __restrict__ emb) {
    int i = blockIdx.x * blockDim.x + threadIdx.x;
    if (i >= BB * EE) return;
    float v = emb[i];
    __nv_bfloat16 h = __float2bfloat16(v);
    g_emb_hi[i] = h;
    g_emb_lo[i] = __float2bfloat16(v - __bfloat162float(h));
}

// ---------------------------------------------------------------------------
// Kernel 3: mma.sync bf16 split-3 GEMM + fused arcface epilogue.
// 256 threads, 2 CTAs/SM (<=128 regs), warp grid 2x4, warp tile 64x32.
// Round-6 proven issue order (term-major, NO warp skew).
// ---------------------------------------------------------------------------
constexpr int ROWB   = 80;                    // padded row bytes (conflict-free)
constexpr int MATB   = 128 * ROWB;            // 10240 B per matrix
constexpr int STAGEB = 4 * MATB;              // 40960 B per stage
constexpr int DYNB   = 2 * STAGEB;            // 81920 B dynamic smem

__global__ __launch_bounds__(256, 2) void gemm_mma_kernel(
    const int* __restrict__ label,
    float* __restrict__ out_logits, float* __restrict__ out_cos)
{
    extern __shared__ char dyn[];
    const int tid  = threadIdx.x;
    const int lane = tid & 31;
    const int wid  = tid >> 5;
    const int wm   = wid >> 2;     // 0..1
    const int wn   = wid & 3;      // 0..3
    const int r0 = blockIdx.x * 128;
    const int c0 = blockIdx.y * 128;
    const uint32_t sbase = smem_u32(dyn);

    // ---- G->S load mapping: 64 threads per matrix, 8 cp.async each ----
    const int mat  = tid >> 6;       // 0:Ahi 1:Alo 2:Bhi 3:Blo
    const int t6   = tid & 63;
    const int ch   = t6 & 3;
    const int rrow = t6 >> 2;
    const __nv_bfloat16* gp;
    if      (mat == 0) gp = g_emb_hi + (size_t)(r0 + rrow) * EE;
    else if (mat == 1) gp = g_emb_lo + (size_t)(r0 + rrow) * EE;
    else if (mat == 2) gp = g_kT_hi + (size_t)(c0 + rrow) * EE;
    else               gp = g_kT_lo + (size_t)(c0 + rrow) * EE;
    const bool isB = (mat >= 2);

    float acc[4][4][4];
    #pragma unroll
    for (int mt = 0; mt < 4; mt++)
        #pragma unroll
        for (int nt = 0; nt < 4; nt++)
            #pragma unroll
            for (int v = 0; v < 4; v++) acc[mt][nt][v] = 0.f;

    auto load_stage = [&](int s, int kc) {
        uint32_t dst0 = sbase + s * STAGEB + mat * MATB + rrow * ROWB + ch * 16;
        const __nv_bfloat16* p = gp + kc * 32 + ch * 8;
        #pragma unroll
        for (int j = 0; j < 8; j++) {
            int sz = 16;
            if (isB && (c0 + rrow + j * 16) >= CC) sz = 0;
            cp16(dst0 + j * 16 * ROWB, p + (size_t)j * 16 * EE, sz);
        }
    };

    // Term-major issue order: same-acc MMAs are 8 issues apart.
    auto compute_stage = [&](int s) {
        const uint32_t st = sbase + s * STAGEB;
        #pragma unroll
        for (int kk = 0; kk < 2; kk++) {
            uint32_t ah[4][4], al[4][4];
            #pragma unroll
            for (int mt = 0; mt < 4; mt++) {
                uint32_t ad = st + (uint32_t)((wm * 64 + mt * 16 + (lane & 15)) * ROWB
                                              + (lane >> 4) * 16 + kk * 32);
                ldsm_x4(ah[mt], ad);
                ldsm_x4(al[mt], ad + MATB);
            }
            #pragma unroll
            for (int np = 0; np < 2; np++) {   // nt pairs (0,1) and (2,3)
                uint32_t bh[4], bl[4];
                uint32_t bd = st + 2 * MATB
                            + (uint32_t)((wn * 32 + (np * 2 + ((lane >> 4) & 1)) * 8
                                          + (lane & 7)) * ROWB
                                         + ((lane >> 3) & 1) * 16 + kk * 32);
                ldsm_x4(bh, bd);
                ldsm_x4(bl, bd + MATB);
                const int n0 = np * 2, n1 = np * 2 + 1;
                // term 1: hi*hi
                #pragma unroll
                for (int mt = 0; mt < 4; mt++) mma_bf16(acc[mt][n0], ah[mt], bh + 0);
                #pragma unroll
                for (int mt = 0; mt < 4; mt++) mma_bf16(acc[mt][n1], ah[mt], bh + 2);
                // term 2: hi*lo
                #pragma unroll
                for (int mt = 0; mt < 4; mt++) mma_bf16(acc[mt][n0], ah[mt], bl + 0);
                #pragma unroll
                for (int mt = 0; mt < 4; mt++) mma_bf16(acc[mt][n1], ah[mt], bl + 2);
                // term 3: lo*hi
                #pragma unroll
                for (int mt = 0; mt < 4; mt++) mma_bf16(acc[mt][n0], al[mt], bh + 0);
                #pragma unroll
                for (int mt = 0; mt < 4; mt++) mma_bf16(acc[mt][n1], al[mt], bh + 2);
            }
        }
    };

    // ---- pipeline: double-buffered over 16 K-chunks of 32 ----
    load_stage(0, 0);
    CP_COMMIT();
    CP_WAIT0();
    __syncthreads();
    for (int kc = 0; kc < 16; kc++) {
        if (kc < 15) { load_stage((kc + 1) & 1, kc + 1); CP_COMMIT(); }
        compute_stage(kc & 1);
        CP_WAIT0();
        __syncthreads();
    }

    // ---- epilogue: arcface + SCALAR stores + per-row partial sum-exp ----
    const int lq = lane >> 2;
    const int lc = 2 * (lane & 3);
    int lbs[4][2];
    #pragma unroll
    for (int mt = 0; mt < 4; mt++) {
        lbs[mt][0] = label[r0 + wm * 64 + mt * 16 + lq];
        lbs[mt][1] = label[r0 + wm * 64 + mt * 16 + lq + 8];
    }

    float rsum[4][2];
    #pragma unroll
    for (int mt = 0; mt < 4; mt++) { rsum[mt][0] = 0.f; rsum[mt][1] = 0.f; }

    const bool full_tile = (c0 + 128 <= CC);   // true for 781/782 strips

    #pragma unroll
    for (int mt = 0; mt < 4; mt++) {
        #pragma unroll
        for (int nt = 0; nt < 4; nt++) {
            #pragma unroll
            for (int v = 0; v < 4; v++) {
                const int h    = v >> 1;
                const int grow = r0 + wm * 64 + mt * 16 + lq + h * 8;
                const int col  = c0 + wn * 32 + nt * 8 + lc + (v & 1);
                if (full_tile || col < CC) {
                    float cs = acc[mt][nt][v];
                    cs = fminf(1.0f, fmaxf(-1.0f, cs));
                    float o = cs;
                    if (col == lbs[mt][h]) {
                        float sn = sqrtf(fmaxf(0.f, 1.0f - cs * cs));
                        float cm = fmaf(cs, COS_M, -sn * SIN_M);
                        o = (cs - THRESH <= 0.f) ? (cs - MM_C) : cm;
                    }
                    float lg = o * S_SCALE;
                    size_t ga = (size_t)grow * CC + col;
                    out_logits[ga] = lg;
                    out_cos[ga]    = cs;
                    rsum[mt][h] += __expf(lg - 64.0f);
                }
            }
        }
    }

    #pragma unroll
    for (int mt = 0; mt < 4; mt++)
        #pragma unroll
        for (int h = 0; h < 2; h++) {
            float s = rsum[mt][h];
            s += __shfl_xor_sync(0xffffffff, s, 1);
            s += __shfl_xor_sync(0xffffffff, s, 2);
            rsum[mt][h] = s;
        }

    float* srows = (float*)dyn;
    if ((lane & 3) == 0) {
        #pragma unroll
        for (int mt = 0; mt < 4; mt++)
            #pragma unroll
            for (int h = 0; h < 2; h++)
                srows[(wm * 64 + mt * 16 + lq + h * 8) * 4 + wn] = rsum[mt][h];
    }
    __syncthreads();
    if (tid < 128) {
        float s = srows[tid * 4 + 0] + srows[tid * 4 + 1]
                + srows[tid * 4 + 2] + srows[tid * 4 + 3];
        g_partial[(size_t)(r0 + tid) * NT + blockIdx.y] = s;
    }
}

// ---------------------------------------------------------------------------
// Kernel 4: per-row reduce of partial sum-exps -> row loss
// ---------------------------------------------------------------------------
__global__ void row_reduce_kernel(const float* __restrict__ out_logits,
                                  const int* __restrict__ label) {
    const int row = blockIdx.x;
    float s = 0.f;
    for (int i = threadIdx.x; i < NT; i += 256)
        s += g_partial[(size_t)row * NT + i];
    __shared__ float sm[256];
    sm[threadIdx.x] = s;
    __syncthreads();
    #pragma unroll
    for (int off = 128; off > 0; off >>= 1) {
        if (threadIdx.x < off) sm[threadIdx.x] += sm[threadIdx.x + off];
        __syncthreads();
    }
    if (threadIdx.x == 0) {
        float logZ = 64.0f + logf(sm[0]);
        g_row_loss[row] = logZ - out_logits[(size_t)row * CC + label[row]];
    }
}

// ---------------------------------------------------------------------------
// Kernel 5: mean over rows -> loss scalar
// ---------------------------------------------------------------------------
__global__ void final_loss_kernel(float* __restrict__ loss_out) {
    __shared__ float sm[BB];
    const int t = threadIdx.x;
    sm[t] = g_row_loss[t];
    __syncthreads();
    #pragma unroll
    for (int off = BB / 2; off > 0; off >>= 1) {
        if (t < off) sm[t] += sm[t + off];
        __syncthreads();
    }
    if (t == 0) loss_out[0] = sm[0] / (float)BB;
}

// ---------------------------------------------------------------------------
extern "C" void kernel_launch(void* const* d_in, const int* in_sizes, int n_in,
                              void* d_out, int out_size) {
    const float* emb   = (const float*)d_in[0];
    const float* ker   = (const float*)d_in[1];
    const int*   label = (const int*)d_in[2];

    float* o          = (float*)d_out;
    float* loss_ptr   = o;
    float* out_logits = o + 1;
    float* out_cos    = o + 1 + (size_t)BB * CC;

    cudaFuncSetAttribute(gemm_mma_kernel,
                         cudaFuncAttributeMaxDynamicSharedMemorySize, DYNB);

    prep_ker_fused<<<CC / 32, 256>>>(ker);     // single pass over ker
    prep_emb_kernel<<<(BB * EE + 255) / 256, 256>>>(emb);

    dim3 grid(4, NT);   // x fastest: adjacent bids share the ker N-strip in L2
    gemm_mma_kernel<<<grid, 256, DYNB>>>(label, out_logits, out_cos);

    row_reduce_kernel<<<BB, 256>>>(out_logits, label);
    final_loss_kernel<<<1, BB>>>(loss_ptr);
}